// round 16
// baseline (speedup 1.0000x reference)
#include <cuda_runtime.h>
#include <math.h>

#define NP    4096
#define NC    45       // cells per side
#define NCELL 2025
#define CPAD  2048
#define CAPT  12       // per-particle collision candidate cap
#define NBLK  4
#define NTHR  1024
#define PPT   4        // NP / NTHR

#define PI_F     3.1415927410125732f
#define TWOPI_F  6.2831854820251465f

// global scratch (no allocation allowed)
static __device__ float2         g_pos[NP];        // translated positions
static __device__ unsigned short g_nbr[CAPT * NP]; // [k][i] collision candidates
static __device__ unsigned char  g_cnt[NP];
static __device__ int            g_done;           // zero-init; reset by sweep block

#define INV_CELL ((float)NC / 1.28e-3f)

// smem union (bytes):
//  pair view : s_p f2[NP] 32K | s_o f2[NP] 32K | s_hc u32[CPAD] 8K |
//              s_scan u32[CPAD] 8K | s_cell u16[NP] 8K | s_srt u16[NP] 8K = 96K
//  sweep view: P0 f2[NP] 32K | P1 f2[NP] 32K | s_nbr u16[CAPT*NP] 96K |
//              s_perm u16[NP] 8K | s_ca u8[NP] 4K = 172K
#define SMEM_BYTES 176128

__global__ void __launch_bounds__(NTHR, 1)
fused_kernel(const float* __restrict__ pre, const float* __restrict__ pim,
             const float* __restrict__ ore, const float* __restrict__ oim,
             const float* __restrict__ deltas, const float* __restrict__ rnoise,
             const float* __restrict__ tnre, const float* __restrict__ tnim,
             float* __restrict__ out) {
    extern __shared__ char smem[];
    // pair view
    float2*         s_p    = (float2*)smem;
    float2*         s_o    = (float2*)(smem + 32768);
    unsigned int*   s_hc   = (unsigned int*)(smem + 65536);
    unsigned int*   s_scan = (unsigned int*)(smem + 73728);
    unsigned short* s_cell = (unsigned short*)(smem + 81920);
    unsigned short* s_srt  = (unsigned short*)(smem + 90112);

    __shared__ float s_ws[64];
    __shared__ float s_cms[2];
    __shared__ int   s_last;
    __shared__ unsigned s_hist[16];

    int tid = threadIdx.x;
    int lane = tid & 31, wrp = tid >> 5;    // 32 warps

    // ---- pair phase A: load + histogram + cms ----
    s_hc[tid] = 0u; s_hc[tid + NTHR] = 0u;
    __syncthreads();

    float ax = 0.f, ay = 0.f;
    #pragma unroll
    for (int s = 0; s < PPT; s++) {
        int k = tid + s * NTHR;
        float px = pre[k], py = pim[k];
        s_p[k] = make_float2(px, py);
        s_o[k] = make_float2(ore[k], oim[k]);
        int cx = (int)(px * INV_CELL); cx = cx < 0 ? 0 : (cx > NC - 1 ? NC - 1 : cx);
        int cy = (int)(py * INV_CELL); cy = cy < 0 ? 0 : (cy > NC - 1 ? NC - 1 : cy);
        int cell = cy * NC + cx;
        s_cell[k] = (unsigned short)cell;
        atomicAdd(&s_hc[cell], 1u);
        ax += px; ay += py;
    }
    #pragma unroll
    for (int o = 16; o > 0; o >>= 1) {
        ax += __shfl_down_sync(0xffffffffu, ax, o);
        ay += __shfl_down_sync(0xffffffffu, ay, o);
    }
    if (lane == 0) { s_ws[wrp] = ax; s_ws[32 + wrp] = ay; }
    __syncthreads();
    if (tid == 0) {
        float sx = 0.f, sy = 0.f;
        #pragma unroll
        for (int w = 0; w < 32; w++) { sx += s_ws[w]; sy += s_ws[32 + w]; }
        s_cms[0] = sx * (1.0f / NP);        // n_a = 4096 exactly
        s_cms[1] = sy * (1.0f / NP);
    }
    __syncthreads();

    // ---- inclusive scan over 2048 cells: 2 cells/thread + warp shfl ----
    {
        unsigned v0, v1;
        int base = tid * 2;
        v0 = s_hc[base];
        v1 = v0 + s_hc[base + 1];
        unsigned tot = v1;
        #pragma unroll
        for (int o = 1; o < 32; o <<= 1) {
            unsigned n = __shfl_up_sync(0xffffffffu, tot, o);
            if (lane >= o) tot += n;
        }
        if (lane == 31) ((unsigned*)s_ws)[wrp] = tot;
        unsigned lanepre = tot - v1;
        __syncthreads();
        unsigned wpre = 0u;
        #pragma unroll
        for (int w = 0; w < 32; w++) { unsigned t = ((unsigned*)s_ws)[w]; if (w < wrp) wpre += t; }
        unsigned off = wpre + lanepre;
        s_scan[base] = v0 + off;
        s_scan[base + 1] = v1 + off;
    }
    __syncthreads();
    {
        int c0 = tid, c1 = tid + NTHR;
        s_hc[c0] = s_scan[c0] - s_hc[c0];   // cursor = exclusive start
        s_hc[c1] = s_scan[c1] - s_hc[c1];
    }
    __syncthreads();
    #pragma unroll
    for (int s = 0; s < PPT; s++) {
        int k = tid + s * NTHR;
        unsigned pos = atomicAdd(&s_hc[s_cell[k]], 1u);
        s_srt[pos] = (unsigned short)k;
    }
    __syncthreads();

    // ---- pair phase B: neighborhood scan for this block's 1024 particles ----
    const float ROCf  = (float)(2.5e-5 + 3.15e-6);   // RO + RC = 28.15um
    const float ROC2G = ROCf * ROCf * 1.0005f;
    const float RRf   = (float)(8e-6);
    const float RCAP  = (float)(4.5 * 3.15e-6);
    const float RCAP2 = RCAP * RCAP;

    int i = blockIdx.x * NTHR + tid;
    float pxi = s_p[i].x, pyi = s_p[i].y;
    float orr = s_o[i].x, ori = s_o[i].y;

    int cell = s_cell[i];
    int cx = cell % NC, cy = cell / NC;
    int x0 = cx > 0 ? cx - 1 : 0, x1 = cx < NC - 1 ? cx + 1 : NC - 1;
    int y0 = cy > 0 ? cy - 1 : 0, y1 = cy < NC - 1 ? cy + 1 : NC - 1;

    float nr = 0.f, sxv = 0.f, syv = 0.f, oxv = 0.f, oyv = 0.f;
    int cc = 0;

    for (int gy = y0; gy <= y1; gy++) {
        int c0 = gy * NC + x0;
        int c1 = gy * NC + x1;
        int b = (c0 == 0) ? 0 : (int)s_scan[c0 - 1];
        int e = (int)s_scan[c1];
        for (int k = b; k < e; k++) {
            int j = s_srt[k];
            float2 pj = s_p[j];
            float dx = pxi - pj.x, dy = pyi - pj.y;
            float r2 = fmaf(dx, dx, dy * dy);
            bool same = (j == i);
            if (r2 <= ROC2G || same) {
                if (r2 <= RCAP2 && !same) {                 // collision candidate
                    if (cc < CAPT) g_nbr[cc * NP + i] = (unsigned short)j;
                    cc++;
                }
                float dist = same ? 1.0f : __fsqrt_rn(r2);  // diag dist = 1 (eye)
                float2 oj = s_o[j];
                if (dist <= ROCf || same) {                 // mask_ro (self incl.)
                    oxv += oj.x;
                    oyv += oj.y;
                }
                if (dist <= RRf && !same) {                 // mask_rr (self excl.)
                    // in_front: |wrap(ang_i - ang_j)| < pi/2 <=> ori_i . ori_j > 0
                    if (fmaf(orr, oj.x, ori * oj.y) > 0.f) {
                        nr += 1.0f; sxv += pj.x; syv += pj.y;
                    }
                }
            }
        }
    }
    g_cnt[i] = (unsigned char)(cc > CAPT ? CAPT : cc);

    // ---- epilogue ----
    float sgn = (nr > 0.f) ? 1.f : 0.f;
    float den = fmaxf(nr, 1.f);
    float SSx = sxv / den - pxi * sgn;
    float SSy = syv / den - pyi * sgn;
    float ddx = -SSx, ddy = -SSy;

    float Px = s_cms[0] - pxi;               // Ps = cms - pos (Ra = inf)
    float Py = s_cms[1] - pyi;

    float del = deltas[i];
    float cd = cosf(del), sd = sinf(del);
    float lx = Px * cd - Py * sd;
    float ly = Px * sd + Py * cd;
    float rxx = Px * cd + Py * sd;
    float ryy = Py * cd - Px * sd;

    float dl = lx * oxv + ly * oyv;
    float dr = rxx * oxv + ryy * oyv;
    float no = fmaxf(__fsqrt_rn(oxv * oxv + oyv * oyv), 1e-14f);
    float cl = dl / (fmaxf(__fsqrt_rn(lx * lx + ly * ly), 1e-14f) * no);
    float cr = dr / (fmaxf(__fsqrt_rn(rxx * rxx + ryy * ryy), 1e-14f) * no);
    bool usel = (cl >= cr);
    float bx = usel ? lx : rxx;
    float by = usel ? ly : ryy;

    bool hasrep = (ddx != 0.f) || (ddy != 0.f);
    float tx = hasrep ? ddx : bx;
    float ty = hasrep ? ddy : by;
    float att = atan2f(ty, tx) - atan2f(ori, orr);
    if (att <= -PI_F) { float r = fmodf(att, PI_F); if (r < 0.f) r += PI_F; att = r; }
    if (att >= PI_F) att -= TWOPI_F;

    const float CTH  = (float)(0.2 * 25.0 * 0.0028);
    const float S2DR = (float)0.07483314773547883;
    const float SDT  = (float)0.4472135954999579;
    float theta = CTH * sinf(att) + rnoise[i] * S2DR * SDT;
    float rc = cosf(theta), rs = sinf(theta);
    float nore = orr * rc - ori * rs;
    float noim = orr * rs + ori * rc;

    const float CH    = (float)0.7071067811865476;
    const float CTT   = (float)1.6733200530681511e-7;
    const float DTVEL = (float)(0.2 * 5e-7);
    float tnr = tnre[i] * CH * CTT;
    float tni = tnim[i] * CH * CTT;
    g_pos[i] = make_float2(pxi + (DTVEL * orr + tnr * SDT),
                           pyi + (DTVEL * ori + tni * SDT));

    out[(1 * NP + i) * 2 + 0] = nore;
    out[(1 * NP + i) * 2 + 1] = noim;
    out[(2 * NP + i) * 2 + 0] = oxv;
    out[(2 * NP + i) * 2 + 1] = oyv;
    out[(3 * NP + i) * 2 + 0] = lx;
    out[(3 * NP + i) * 2 + 1] = ly;
    out[(4 * NP + i) * 2 + 0] = rxx;
    out[(4 * NP + i) * 2 + 1] = ryy;

    // ---- last-block ticket ----
    __syncthreads();
    if (tid == 0) {
        __threadfence();
        int v = atomicAdd(&g_done, 1);
        s_last = (v == NBLK - 1) ? 1 : 0;
    }
    __syncthreads();
    if (!s_last) return;
    __threadfence();   // acquire all blocks' g_pos / g_nbr / g_cnt writes

    // ---- sweep phase (last block): cnt-sorted, register-resident indices ----
    float2*         P0     = (float2*)smem;
    float2*         P1     = (float2*)(smem + 32768);
    unsigned short* s_nbr  = (unsigned short*)(smem + 65536);   // 96K
    unsigned short* s_perm = (unsigned short*)(smem + 163840);  // 8K
    unsigned char*  s_ca   = (unsigned char*)(smem + 172032);   // 4K

    #pragma unroll
    for (int s = 0; s < PPT; s++) {
        int k = tid + s * NTHR;
        float2 v = g_pos[k];
        P0[k] = v;
        P1[k] = v;          // cnt==0 particles never written again: valid in both
        s_ca[k] = g_cnt[k];
    }
    {
        const uint4* src = (const uint4*)g_nbr;   // 96KB = 6144 uint4
        uint4* dst = (uint4*)s_nbr;
        #pragma unroll
        for (int s = 0; s < 6; s++) dst[tid + s * NTHR] = src[tid + s * NTHR];
    }
    if (tid < 16) s_hist[tid] = 0u;
    __syncthreads();

    // counting sort by candidate count (13 bins)
    #pragma unroll
    for (int s = 0; s < PPT; s++)
        atomicAdd(&s_hist[s_ca[tid + s * NTHR]], 1u);
    __syncthreads();
    if (tid == 0) {
        unsigned run = 0u;
        #pragma unroll
        for (int b = 0; b <= CAPT; b++) { unsigned c = s_hist[b]; s_hist[b] = run; run += c; }
    }
    __syncthreads();
    #pragma unroll
    for (int s = 0; s < PPT; s++) {
        int p = tid + s * NTHR;
        unsigned pos = atomicAdd(&s_hist[s_ca[p]], 1u);
        s_perm[pos] = (unsigned short)p;
    }
    __syncthreads();

    // preload per-thread particle ids, counts, and PACKED candidate indices
    int pp[PPT], myc[PPT];
    unsigned pk[PPT][CAPT / 2];           // 2 x u16 per reg
    #pragma unroll
    for (int s = 0; s < PPT; s++) {
        pp[s] = s_perm[tid + s * NTHR];
        int cnt = s_ca[pp[s]];
        myc[s] = cnt;
        #pragma unroll
        for (int w = 0; w < CAPT / 2; w++) {
            unsigned lo = (2 * w     < cnt) ? s_nbr[(2 * w) * NP + pp[s]]     : 0u;
            unsigned hi = (2 * w + 1 < cnt) ? s_nbr[(2 * w + 1) * NP + pp[s]] : 0u;
            pk[s][w] = lo | (hi << 16);
        }
    }
    __syncthreads();

    const float THR   = (float)(2.0 * 3.15e-6);     // 2*Rc
    const float THR2G = THR * THR * 1.0005f;
    const float MOVC  = (float)(2.1 * 3.15e-6);

    float2* C = P0;
    float2* N = P1;
    for (int t = 0; t < 30; t++) {
        int mycoll = 0;
        #pragma unroll
        for (int s = 0; s < PPT; s++) {
            int cnt = myc[s];
            if (cnt > 0) {
                int p = pp[s];
                float2 pc = C[p];
                float mx = 0.f, my = 0.f;
                #pragma unroll
                for (int k = 0; k < CAPT; k++) {
                    if (k < cnt) {
                        int j = (pk[s][k >> 1] >> ((k & 1) * 16)) & 0xffff;
                        float2 q = C[j];
                        float dx = q.x - pc.x, dy = q.y - pc.y;   // p_j - p_i
                        float r2 = fmaf(dx, dx, dy * dy);
                        if (r2 <= THR2G) {
                            float rinv = __frsqrt_rn(r2);
                            float absd = r2 * rinv;
                            if (absd <= THR) {
                                float f = (MOVC - absd) * 0.5f * rinv;
                                mx += dx * f;
                                my += dy * f;
                                mycoll = 1;
                            }
                        }
                    }
                }
                N[p] = make_float2(pc.x - mx, pc.y - my);   // write to OTHER buffer
            }
        }
        int any = __syncthreads_or(mycoll);   // single barrier per iteration
        float2* tmp = C; C = N; N = tmp;
        if (!any) break;                      // uniform decision
    }

    #pragma unroll
    for (int s = 0; s < PPT; s++) {
        int p = tid + s * NTHR;
        out[p * 2 + 0] = C[p].x;
        out[p * 2 + 1] = C[p].y;
    }
    if (tid == 0) g_done = 0;                 // reset for next graph replay
}

// ---------------------------------------------------------------------------
extern "C" void kernel_launch(void* const* d_in, const int* in_sizes, int n_in,
                              void* d_out, int out_size) {
    const float* pre    = (const float*)d_in[0];
    const float* pim    = (const float*)d_in[1];
    const float* ore    = (const float*)d_in[2];
    const float* oim    = (const float*)d_in[3];
    const float* deltas = (const float*)d_in[4];
    const float* rnoise = (const float*)d_in[5];
    const float* tnre   = (const float*)d_in[6];
    const float* tnim   = (const float*)d_in[7];
    float* out = (float*)d_out;

    cudaFuncSetAttribute(fused_kernel, cudaFuncAttributeMaxDynamicSharedMemorySize, SMEM_BYTES);
    fused_kernel<<<NBLK, NTHR, SMEM_BYTES>>>(pre, pim, ore, oim, deltas, rnoise,
                                             tnre, tnim, out);
}